// round 2
// baseline (speedup 1.0000x reference)
#include <cuda_runtime.h>
#include <math.h>

#define B   2
#define NT  2048
#define DM  1024
#define H   16
#define HD  64
#define EPSF 1e-10f

// ---------------- scratch (device globals; no allocations) ----------------
__device__ float g_Q[(size_t)B*H*NT*HD];
__device__ float g_K[(size_t)B*H*NT*HD];
__device__ float g_V[(size_t)B*H*NT*HD];
__device__ float g_A[(size_t)B*H*NT*NT];     // scores -> attention (536 MB)
__device__ float g_P[(size_t)B*NT*NT];       // sinkhorn matrix (33.5 MB)
__device__ float g_ctx[(size_t)B*NT*DM];     // attention output context
__device__ float g_enth[(size_t)B*H*NT];     // per-(b,h,row) entropy
__device__ float g_colsum[(size_t)B*NT];

// ---------------------------------------------------------------------------
// NT GEMM: C[m][e] = sum_k A[m][k] * W[e][k] + bias[e]
// BM=BN=64, BK=16, 256 threads, 4x4 per thread.
// head_layout: 0 -> C row-major MxN; 1 -> C[((b*H+h)*NT+tok)*HD+hd]
// ---------------------------------------------------------------------------
__global__ __launch_bounds__(256)
void gemm_nt(const float* __restrict__ A, const float* __restrict__ W,
             const float* __restrict__ bias, float* __restrict__ C,
             int M, int N, int K, int head_layout)
{
    __shared__ float As[16][64];
    __shared__ float Bs[16][64];
    const int tid = threadIdx.x;
    const int tx = tid & 15, ty = tid >> 4;
    const int bm0 = blockIdx.y * 64, bn0 = blockIdx.x * 64;

    const int lr = tid >> 2;          // 0..63 row within tile
    const int lc = (tid & 3) * 4;     // 0,4,8,12 k within tile
    const float* Ag = A + (size_t)(bm0 + lr) * K + lc;
    const float* Wg = W + (size_t)(bn0 + lr) * K + lc;

    float acc[4][4] = {};

    for (int k0 = 0; k0 < K; k0 += 16) {
        float4 av = *(const float4*)(Ag + k0);
        float4 wv = *(const float4*)(Wg + k0);
        As[lc+0][lr] = av.x; As[lc+1][lr] = av.y; As[lc+2][lr] = av.z; As[lc+3][lr] = av.w;
        Bs[lc+0][lr] = wv.x; Bs[lc+1][lr] = wv.y; Bs[lc+2][lr] = wv.z; Bs[lc+3][lr] = wv.w;
        __syncthreads();
        #pragma unroll
        for (int k = 0; k < 16; k++) {
            float4 a4 = *(const float4*)&As[k][ty*4];
            float4 b4 = *(const float4*)&Bs[k][tx*4];
            float ar[4] = {a4.x, a4.y, a4.z, a4.w};
            float br[4] = {b4.x, b4.y, b4.z, b4.w};
            #pragma unroll
            for (int i = 0; i < 4; i++)
                #pragma unroll
                for (int j = 0; j < 4; j++)
                    acc[i][j] += ar[i] * br[j];
        }
        __syncthreads();
    }

    #pragma unroll
    for (int i = 0; i < 4; i++) {
        int m = bm0 + ty*4 + i;
        #pragma unroll
        for (int j = 0; j < 4; j++) {
            int e = bn0 + tx*4 + j;
            float v = acc[i][j] + bias[e];
            if (head_layout) {
                int bb = m >> 11, tok = m & 2047;
                int h = e >> 6, hd = e & 63;
                C[(((size_t)(bb*H + h)*NT + tok)*HD) + hd] = v;
            } else {
                C[(size_t)m * N + e] = v;
            }
        }
    }
}

// ---------------------------------------------------------------------------
// Scores: S[bh][i][j] = dot(Q_i,K_j)/8 - |pf_i - pf_j| * |pbs[h]|
// ---------------------------------------------------------------------------
__global__ __launch_bounds__(256)
void scores_kernel(const float* __restrict__ pbs, const int* __restrict__ perm)
{
    const int bh = blockIdx.z;
    const int b = bh >> 4, h = bh & 15;
    const int bi0 = blockIdx.y * 64, bj0 = blockIdx.x * 64;

    __shared__ float Qs[64][64];   // [k][i]
    __shared__ float Ks[64][64];   // [k][j]
    __shared__ float pfi[64], pfj[64];

    const int tid = threadIdx.x;
    const int tx = tid & 15, ty = tid >> 4;

    const float* Qg = g_Q + ((size_t)bh*NT + bi0) * HD;
    const float* Kg = g_K + ((size_t)bh*NT + bj0) * HD;

    const int lr = tid >> 2;          // 0..63
    const int lc = (tid & 3) * 16;    // 0,16,32,48
    #pragma unroll
    for (int u = 0; u < 4; u++) {
        float4 qv = *(const float4*)(Qg + (size_t)lr*HD + lc + u*4);
        float4 kv = *(const float4*)(Kg + (size_t)lr*HD + lc + u*4);
        Qs[lc+u*4+0][lr]=qv.x; Qs[lc+u*4+1][lr]=qv.y; Qs[lc+u*4+2][lr]=qv.z; Qs[lc+u*4+3][lr]=qv.w;
        Ks[lc+u*4+0][lr]=kv.x; Ks[lc+u*4+1][lr]=kv.y; Ks[lc+u*4+2][lr]=kv.z; Ks[lc+u*4+3][lr]=kv.w;
    }
    if (tid < 64)       pfi[tid]     = (float)perm[b*NT + bi0 + tid];
    else if (tid < 128) pfj[tid-64]  = (float)perm[b*NT + bj0 + (tid-64)];
    __syncthreads();

    float acc[4][4] = {};
    #pragma unroll 16
    for (int k = 0; k < 64; k++) {
        float4 a4 = *(const float4*)&Qs[k][ty*4];
        float4 b4 = *(const float4*)&Ks[k][tx*4];
        float ar[4] = {a4.x, a4.y, a4.z, a4.w};
        float br[4] = {b4.x, b4.y, b4.z, b4.w};
        #pragma unroll
        for (int i = 0; i < 4; i++)
            #pragma unroll
            for (int j = 0; j < 4; j++)
                acc[i][j] += ar[i] * br[j];
    }

    const float pb = fabsf(pbs[h]);
    #pragma unroll
    for (int i = 0; i < 4; i++) {
        int ii = ty*4 + i;
        #pragma unroll
        for (int j = 0; j < 4; j++) {
            int jj = tx*4 + j;
            float v = acc[i][j] * 0.125f - fabsf(pfi[ii] - pfj[jj]) * pb;
            g_A[((size_t)bh*NT + (bi0+ii))*NT + (bj0+jj)] = v;
        }
    }
}

// ---------------------------------------------------------------------------
// Row softmax (in place on g_A) + row entropy -> g_enth
// ---------------------------------------------------------------------------
__global__ __launch_bounds__(256)
void softmax_ent_kernel()
{
    const size_t row = blockIdx.x;              // 0 .. B*H*NT-1
    float* rp = g_A + row * NT;
    const int tid = threadIdx.x;
    __shared__ float red[256];

    float v[8];
    float mx = -INFINITY;
    #pragma unroll
    for (int s = 0; s < 8; s++) { v[s] = rp[tid + s*256]; mx = fmaxf(mx, v[s]); }

    red[tid] = mx; __syncthreads();
    for (int o = 128; o > 0; o >>= 1) { if (tid < o) red[tid] = fmaxf(red[tid], red[tid+o]); __syncthreads(); }
    mx = red[0]; __syncthreads();

    float sum = 0.f;
    #pragma unroll
    for (int s = 0; s < 8; s++) { v[s] = expf(v[s] - mx); sum += v[s]; }
    red[tid] = sum; __syncthreads();
    for (int o = 128; o > 0; o >>= 1) { if (tid < o) red[tid] += red[tid+o]; __syncthreads(); }
    sum = red[0]; __syncthreads();

    const float inv = 1.0f / sum;
    float ent = 0.f;
    #pragma unroll
    for (int s = 0; s < 8; s++) {
        float p = v[s] * inv;
        rp[tid + s*256] = p;
        ent -= p * logf(p + EPSF);
    }
    red[tid] = ent; __syncthreads();
    for (int o = 128; o > 0; o >>= 1) { if (tid < o) red[tid] += red[tid+o]; __syncthreads(); }
    if (tid == 0) g_enth[row] = red[0];
}

// ---------------------------------------------------------------------------
// AV: ctx[b, i, h*64+hd] = sum_j A[bh][i][j] * V[bh][j][hd]
// ---------------------------------------------------------------------------
__global__ __launch_bounds__(256)
void av_kernel()
{
    const int bh = blockIdx.z;
    const int b = bh >> 4, h = bh & 15;
    const int bi0 = blockIdx.y * 64;

    __shared__ float As[16][64];   // [k][i]
    __shared__ float Vs[16][64];   // [k][hd]
    const int tid = threadIdx.x;
    const int tx = tid & 15, ty = tid >> 4;

    const float* Ap = g_A + ((size_t)bh*NT + bi0) * NT;
    const float* Vp = g_V + (size_t)bh * NT * HD;

    const int lr = tid >> 2, lc = (tid & 3) * 4;     // A tile load
    const int vkr = tid >> 4, vc = (tid & 15) * 4;   // V tile load

    float acc[4][4] = {};

    for (int k0 = 0; k0 < NT; k0 += 16) {
        float4 av = *(const float4*)(Ap + (size_t)lr*NT + k0 + lc);
        As[lc+0][lr]=av.x; As[lc+1][lr]=av.y; As[lc+2][lr]=av.z; As[lc+3][lr]=av.w;
        *(float4*)&Vs[vkr][vc] = *(const float4*)(Vp + (size_t)(k0+vkr)*HD + vc);
        __syncthreads();
        #pragma unroll
        for (int k = 0; k < 16; k++) {
            float4 a4 = *(const float4*)&As[k][ty*4];
            float4 b4 = *(const float4*)&Vs[k][tx*4];
            float ar[4] = {a4.x, a4.y, a4.z, a4.w};
            float br[4] = {b4.x, b4.y, b4.z, b4.w};
            #pragma unroll
            for (int i = 0; i < 4; i++)
                #pragma unroll
                for (int j = 0; j < 4; j++)
                    acc[i][j] += ar[i] * br[j];
        }
        __syncthreads();
    }

    #pragma unroll
    for (int i = 0; i < 4; i++) {
        int tok = bi0 + ty*4 + i;
        #pragma unroll
        for (int j = 0; j < 4; j++) {
            int hd = tx*4 + j;
            g_ctx[((size_t)b*NT + tok)*DM + h*HD + hd] = acc[i][j];
        }
    }
}

// ---------------------------------------------------------------------------
// P = exp(log(mean_h A + EPS) / 0.1)
// ---------------------------------------------------------------------------
__global__ __launch_bounds__(256)
void build_P_kernel()
{
    size_t idx = (size_t)blockIdx.x * 256 + threadIdx.x;   // 0 .. B*NT*NT-1
    size_t b = idx / ((size_t)NT*NT);
    size_t rem = idx - b * (size_t)NT*NT;
    float s = 0.f;
    #pragma unroll
    for (int h = 0; h < H; h++)
        s += g_A[((size_t)(b*H + h))*NT*NT + rem];
    float avg = s * (1.0f / 16.0f);
    g_P[idx] = expf(logf(avg + EPSF) / 0.1f);
}

// ---------------------------------------------------------------------------
// Sinkhorn pieces
// ---------------------------------------------------------------------------
__global__ __launch_bounds__(256)
void rownorm_kernel()
{
    const size_t row = blockIdx.x;     // 0..B*NT-1
    float* rp = g_P + row * NT;
    const int tid = threadIdx.x;
    __shared__ float red[256];
    float v[8]; float s = 0.f;
    #pragma unroll
    for (int k = 0; k < 8; k++) { v[k] = rp[tid + k*256]; s += v[k]; }
    red[tid] = s; __syncthreads();
    for (int o = 128; o > 0; o >>= 1) { if (tid < o) red[tid] += red[tid+o]; __syncthreads(); }
    float inv = 1.0f / (red[0] + EPSF);
    #pragma unroll
    for (int k = 0; k < 8; k++) rp[tid + k*256] = v[k] * inv;
}

__global__ __launch_bounds__(256)
void colsum_kernel()
{
    const int j = blockIdx.x * 256 + threadIdx.x;   // 0..NT-1
    const int b = blockIdx.y;
    const float* p = g_P + (size_t)b*NT*NT + j;
    float s = 0.f;
    for (int i = 0; i < NT; i++) s += p[(size_t)i*NT];
    g_colsum[b*NT + j] = s;
}

__global__ __launch_bounds__(256)
void coldiv_kernel()
{
    size_t idx = (size_t)blockIdx.x * 256 + threadIdx.x;
    size_t b = idx / ((size_t)NT*NT);
    int j = (int)(idx % NT);
    g_P[idx] = g_P[idx] / (g_colsum[b*NT + j] + EPSF);
}

// ---------------------------------------------------------------------------
// Certainty update
// ---------------------------------------------------------------------------
__global__ __launch_bounds__(256)
void cert_kernel(const float* __restrict__ cert, const float* __restrict__ ctemp,
                 float* __restrict__ out)
{
    const int idx = blockIdx.x * 256 + threadIdx.x;  // 0..B*NT-1
    const int b = idx >> 11, i = idx & 2047;
    float s = 0.f;
    #pragma unroll
    for (int h = 0; h < H; h++) s += g_enth[(size_t)(b*H + h)*NT + i];
    float ent = s * (1.0f / 16.0f);
    float z = ctemp[0] * (logf(2048.0f) - ent);
    float cu = 1.0f / (1.0f + expf(-z));
    out[idx] = fmaxf(cert[idx], cu);
}

// ---------------------------------------------------------------------------
// Row argmax of P (first max wins) + gather of old permutation
// ---------------------------------------------------------------------------
__global__ __launch_bounds__(256)
void argmax_gather_kernel(const int* __restrict__ perm, float* __restrict__ out)
{
    const int row = blockIdx.x;          // 0..B*NT-1
    const int b = row >> 11;
    const float* rp = g_P + (size_t)row * NT;
    const int tid = threadIdx.x;
    __shared__ float bv[256];
    __shared__ int   bi[256];

    float best = -INFINITY; int bj = NT;
    #pragma unroll
    for (int s = 0; s < 8; s++) {
        int j = tid + s*256;
        float v = rp[j];
        if (v > best) { best = v; bj = j; }
    }
    bv[tid] = best; bi[tid] = bj; __syncthreads();
    for (int o = 128; o > 0; o >>= 1) {
        if (tid < o) {
            if (bv[tid+o] > bv[tid] || (bv[tid+o] == bv[tid] && bi[tid+o] < bi[tid])) {
                bv[tid] = bv[tid+o]; bi[tid] = bi[tid+o];
            }
        }
        __syncthreads();
    }
    if (tid == 0) out[row] = (float)perm[(size_t)b*NT + bi[0]];
}

// ---------------------------------------------------------------------------
extern "C" void kernel_launch(void* const* d_in, const int* in_sizes, int n_in,
                              void* d_out, int out_size)
{
    const float* x     = (const float*)d_in[0];
    const float* cert  = (const float*)d_in[1];
    const int*   perm  = (const int*)  d_in[2];   // jax x64 disabled -> int32
    const float* Wq    = (const float*)d_in[3];
    const float* bq    = (const float*)d_in[4];
    const float* Wk    = (const float*)d_in[5];
    const float* bk    = (const float*)d_in[6];
    const float* Wv    = (const float*)d_in[7];
    const float* bv    = (const float*)d_in[8];
    const float* Wo    = (const float*)d_in[9];
    const float* bo    = (const float*)d_in[10];
    const float* pbs   = (const float*)d_in[11];
    const float* ctemp = (const float*)d_in[12];
    float* out = (float*)d_out;

    float *pQ, *pK, *pV, *pCtx;
    cudaGetSymbolAddress((void**)&pQ,   g_Q);
    cudaGetSymbolAddress((void**)&pK,   g_K);
    cudaGetSymbolAddress((void**)&pV,   g_V);
    cudaGetSymbolAddress((void**)&pCtx, g_ctx);

    const int M = B * NT;                 // 4096

    // QKV projections into head layout
    dim3 gProj(DM/64, M/64);              // (16, 64)
    gemm_nt<<<gProj, 256>>>(x, Wq, bq, pQ, M, DM, DM, 1);
    gemm_nt<<<gProj, 256>>>(x, Wk, bk, pK, M, DM, DM, 1);
    gemm_nt<<<gProj, 256>>>(x, Wv, bv, pV, M, DM, DM, 1);

    // Scores with permutation-distance bias
    dim3 gScore(NT/64, NT/64, B*H);       // (32, 32, 32)
    scores_kernel<<<gScore, 256>>>(pbs, perm);

    // Softmax + entropy (in place)
    softmax_ent_kernel<<<B*H*NT, 256>>>();

    // Attention @ V
    dim3 gAV(1, NT/64, B*H);
    av_kernel<<<gAV, 256>>>();

    // Output projection -> out[0 .. 4194303]
    gemm_nt<<<gProj, 256>>>(pCtx, Wo, bo, out, M, DM, DM, 0);

    // Certainty -> out[4194304 .. 4198399]
    cert_kernel<<<(B*NT)/256, 256>>>(cert, ctemp, out + (size_t)M*DM);

    // Sinkhorn
    build_P_kernel<<<(B*NT*NT)/256, 256>>>();
    for (int it = 0; it < 10; it++) {
        rownorm_kernel<<<B*NT, 256>>>();
        colsum_kernel<<<dim3(NT/256, B), 256>>>();
        coldiv_kernel<<<(B*NT*NT)/256, 256>>>();
    }

    // Argmax + gather -> out[4198400 .. 4202495]
    argmax_gather_kernel<<<B*NT, 256>>>(perm, out + (size_t)M*DM + B*NT);
}

// round 3
// speedup vs baseline: 1.3504x; 1.3504x over previous
#include <cuda_runtime.h>
#include <math.h>

#define B   2
#define NT  2048
#define DM  1024
#define H   16
#define HD  64
#define EPSF 1e-10f

typedef unsigned long long u64;

__device__ float g_Q[(size_t)B*H*NT*HD];
__device__ float g_K[(size_t)B*H*NT*HD];
__device__ float g_V[(size_t)B*H*NT*HD];
__device__ float g_E[(size_t)B*H*NT*NT];     // exp(scores), unnormalized
__device__ float g_P[(size_t)B*NT*NT];
__device__ float g_ctx[(size_t)B*NT*DM];
__device__ float g_Z[(size_t)B*H*NT];
__device__ float g_T[(size_t)B*H*NT];
__device__ float g_Zi[(size_t)B*H*NT];
__device__ float g_colsum[B*NT];

__device__ __forceinline__ u64 splat2(float x){
    u64 r; asm("mov.b64 %0, {%1,%1};" : "=l"(r) : "f"(x)); return r;
}
__device__ __forceinline__ void fma2(u64 &d, u64 a, u64 b){
    asm("fma.rn.f32x2 %0, %1, %2, %0;" : "+l"(d) : "l"(a), "l"(b));
}
__device__ __forceinline__ float2 unpk(u64 v){
    float2 r; asm("mov.b64 {%0,%1}, %2;" : "=f"(r.x), "=f"(r.y) : "l"(v)); return r;
}

// ---------------------------------------------------------------------------
// C[m][e] = sum_k A[m][k]*W[e][k] + bias[e].  128x128 tile, BK=16, 8x8/thread.
// ---------------------------------------------------------------------------
__global__ __launch_bounds__(256)
void gemm_nt2(const float* __restrict__ A, const float* __restrict__ W,
              const float* __restrict__ bias, float* __restrict__ C,
              int N, int K, int head_layout)
{
    __shared__ __align__(16) float As[16][132];
    __shared__ __align__(16) float Bs[16][132];
    const int tid = threadIdx.x;
    const int tx = tid & 15, ty = tid >> 4;
    const int bm0 = blockIdx.y * 128, bn0 = blockIdx.x * 128;
    const int lr = tid >> 1, lk = (tid & 1) * 8;
    const float* Ag = A + (size_t)(bm0 + lr) * K + lk;
    const float* Wg = W + (size_t)(bn0 + lr) * K + lk;

    u64 acc[4][8];
    #pragma unroll
    for (int i = 0; i < 4; i++)
        #pragma unroll
        for (int j = 0; j < 8; j++) acc[i][j] = 0ull;

    for (int k0 = 0; k0 < K; k0 += 16) {
        float4 a0 = *(const float4*)(Ag + k0);
        float4 a1 = *(const float4*)(Ag + k0 + 4);
        float4 w0 = *(const float4*)(Wg + k0);
        float4 w1 = *(const float4*)(Wg + k0 + 4);
        __syncthreads();
        As[lk+0][lr]=a0.x; As[lk+1][lr]=a0.y; As[lk+2][lr]=a0.z; As[lk+3][lr]=a0.w;
        As[lk+4][lr]=a1.x; As[lk+5][lr]=a1.y; As[lk+6][lr]=a1.z; As[lk+7][lr]=a1.w;
        Bs[lk+0][lr]=w0.x; Bs[lk+1][lr]=w0.y; Bs[lk+2][lr]=w0.z; Bs[lk+3][lr]=w0.w;
        Bs[lk+4][lr]=w1.x; Bs[lk+5][lr]=w1.y; Bs[lk+6][lr]=w1.z; Bs[lk+7][lr]=w1.w;
        __syncthreads();
        #pragma unroll
        for (int k = 0; k < 16; k++) {
            ulonglong2 m0 = *(const ulonglong2*)&As[k][ty*4];
            ulonglong2 m1 = *(const ulonglong2*)&As[k][64+ty*4];
            float4 b0 = *(const float4*)&Bs[k][tx*4];
            float4 b1 = *(const float4*)&Bs[k][64+tx*4];
            u64 ap[4] = {m0.x, m0.y, m1.x, m1.y};
            u64 bs8[8] = {splat2(b0.x),splat2(b0.y),splat2(b0.z),splat2(b0.w),
                          splat2(b1.x),splat2(b1.y),splat2(b1.z),splat2(b1.w)};
            #pragma unroll
            for (int i = 0; i < 4; i++)
                #pragma unroll
                for (int j = 0; j < 8; j++)
                    fma2(acc[i][j], ap[i], bs8[j]);
        }
    }

    #pragma unroll
    for (int i = 0; i < 4; i++) {
        int r = (i < 2) ? ty*4 + 2*i : 64 + ty*4 + 2*(i-2);
        int m0 = bm0 + r;
        float2 t[8];
        #pragma unroll
        for (int j = 0; j < 8; j++) t[j] = unpk(acc[i][j]);
        #pragma unroll
        for (int half = 0; half < 2; half++) {
            int e0 = bn0 + half*64 + tx*4;
            float b0v=bias[e0], b1v=bias[e0+1], b2v=bias[e0+2], b3v=bias[e0+3];
            float4 r0 = make_float4(t[half*4+0].x+b0v, t[half*4+1].x+b1v,
                                    t[half*4+2].x+b2v, t[half*4+3].x+b3v);
            float4 r1 = make_float4(t[half*4+0].y+b0v, t[half*4+1].y+b1v,
                                    t[half*4+2].y+b2v, t[half*4+3].y+b3v);
            float *p0, *p1;
            if (head_layout) {
                int bb = m0 >> 11, tok = m0 & 2047, hh = e0 >> 6, hd = e0 & 63;
                p0 = C + (((size_t)(bb*H + hh)*NT + tok)*HD) + hd;
                p1 = p0 + HD;
            } else {
                p0 = C + (size_t)m0*N + e0; p1 = p0 + N;
            }
            *(float4*)p0 = r0;
            *(float4*)p1 = r1;
        }
    }
}

// ---------------------------------------------------------------------------
// Fused scores + exp + row Z/T.  Block = 128-row strip of one (b,h); sweeps j.
// ---------------------------------------------------------------------------
__global__ __launch_bounds__(256)
void scores_exp_kernel(const float* __restrict__ pbs, const int* __restrict__ perm)
{
    __shared__ __align__(16) float Qs[64][132];
    __shared__ __align__(16) float Ks[16][132];
    __shared__ float pfi[128], pfj[128];

    const int tid = threadIdx.x;
    const int tx = tid & 15, ty = tid >> 4;
    const int bh = blockIdx.y;
    const int b = bh >> 4, h = bh & 15;
    const int bi0 = blockIdx.x * 128;
    const float pb = fabsf(pbs[h]);

    const float* Qg = g_Q + ((size_t)bh*NT + bi0)*HD;
    const int row = tid >> 1, kb = (tid & 1) * 8;
    #pragma unroll
    for (int c = 0; c < 4; c++) {
        int kk = kb + c*16;
        float4 q0 = *(const float4*)(Qg + (size_t)row*HD + kk);
        float4 q1 = *(const float4*)(Qg + (size_t)row*HD + kk + 4);
        Qs[kk+0][row]=q0.x; Qs[kk+1][row]=q0.y; Qs[kk+2][row]=q0.z; Qs[kk+3][row]=q0.w;
        Qs[kk+4][row]=q1.x; Qs[kk+5][row]=q1.y; Qs[kk+6][row]=q1.z; Qs[kk+7][row]=q1.w;
    }
    if (tid < 128) pfi[tid] = (float)perm[b*NT + bi0 + tid];

    float Zr[8] = {0,0,0,0,0,0,0,0};
    float Tr[8] = {0,0,0,0,0,0,0,0};

    for (int j0 = 0; j0 < NT; j0 += 128) {
        __syncthreads();
        if (tid < 128) pfj[tid] = (float)perm[b*NT + j0 + tid];

        u64 acc[4][8];
        #pragma unroll
        for (int i = 0; i < 4; i++)
            #pragma unroll
            for (int j = 0; j < 8; j++) acc[i][j] = 0ull;

        const float* Kg = g_K + ((size_t)bh*NT + j0)*HD;
        for (int kc = 0; kc < 64; kc += 16) {
            float4 k0v = *(const float4*)(Kg + (size_t)row*HD + kc + kb);
            float4 k1v = *(const float4*)(Kg + (size_t)row*HD + kc + kb + 4);
            __syncthreads();
            Ks[kb+0][row]=k0v.x; Ks[kb+1][row]=k0v.y; Ks[kb+2][row]=k0v.z; Ks[kb+3][row]=k0v.w;
            Ks[kb+4][row]=k1v.x; Ks[kb+5][row]=k1v.y; Ks[kb+6][row]=k1v.z; Ks[kb+7][row]=k1v.w;
            __syncthreads();
            #pragma unroll
            for (int k = 0; k < 16; k++) {
                ulonglong2 m0 = *(const ulonglong2*)&Qs[kc+k][ty*4];
                ulonglong2 m1 = *(const ulonglong2*)&Qs[kc+k][64+ty*4];
                float4 b0 = *(const float4*)&Ks[k][tx*4];
                float4 b1 = *(const float4*)&Ks[k][64+tx*4];
                u64 ap[4] = {m0.x, m0.y, m1.x, m1.y};
                u64 bs8[8] = {splat2(b0.x),splat2(b0.y),splat2(b0.z),splat2(b0.w),
                              splat2(b1.x),splat2(b1.y),splat2(b1.z),splat2(b1.w)};
                #pragma unroll
                for (int i = 0; i < 4; i++)
                    #pragma unroll
                    for (int j = 0; j < 8; j++)
                        fma2(acc[i][j], ap[i], bs8[j]);
            }
        }

        #pragma unroll
        for (int i = 0; i < 4; i++) {
            int rl = (i < 2) ? ty*4 + 2*i : 64 + ty*4 + 2*(i-2);
            float pfa = pfi[rl], pfb = pfi[rl+1];
            float2 t[8];
            #pragma unroll
            for (int j = 0; j < 8; j++) t[j] = unpk(acc[i][j]);
            #pragma unroll
            for (int half = 0; half < 2; half++) {
                int cl = half*64 + tx*4;
                float e0[4], e1[4];
                #pragma unroll
                for (int q = 0; q < 4; q++) {
                    float d = pfj[cl+q];
                    float s0 = t[half*4+q].x * 0.125f - fabsf(pfa - d) * pb;
                    float s1 = t[half*4+q].y * 0.125f - fabsf(pfb - d) * pb;
                    float x0 = __expf(s0), x1 = __expf(s1);
                    Zr[2*i]   += x0; Tr[2*i]   += s0*x0;
                    Zr[2*i+1] += x1; Tr[2*i+1] += s1*x1;
                    e0[q] = x0; e1[q] = x1;
                }
                size_t base = ((size_t)bh*NT + bi0 + rl)*NT + j0 + cl;
                *(float4*)(g_E + base)      = make_float4(e0[0],e0[1],e0[2],e0[3]);
                *(float4*)(g_E + base + NT) = make_float4(e1[0],e1[1],e1[2],e1[3]);
            }
        }
    }

    float* red = &Ks[0][0];
    __syncthreads();
    #pragma unroll
    for (int i = 0; i < 4; i++) {
        int r0 = (i < 2) ? ty*4 + 2*i : 64 + ty*4 + 2*(i-2);
        red[tx*128 + r0] = Zr[2*i]; red[tx*128 + r0 + 1] = Zr[2*i+1];
    }
    __syncthreads();
    if (tid < 128) {
        float s = 0.f;
        #pragma unroll
        for (int t = 0; t < 16; t++) s += red[t*128 + tid];
        g_Z[(size_t)bh*NT + bi0 + tid] = s;
    }
    __syncthreads();
    #pragma unroll
    for (int i = 0; i < 4; i++) {
        int r0 = (i < 2) ? ty*4 + 2*i : 64 + ty*4 + 2*(i-2);
        red[tx*128 + r0] = Tr[2*i]; red[tx*128 + r0 + 1] = Tr[2*i+1];
    }
    __syncthreads();
    if (tid < 128) {
        float s = 0.f;
        #pragma unroll
        for (int t = 0; t < 16; t++) s += red[t*128 + tid];
        g_T[(size_t)bh*NT + bi0 + tid] = s;
    }
}

__global__ __launch_bounds__(256)
void zinv_kernel()
{
    int i = blockIdx.x * 256 + threadIdx.x;
    g_Zi[i] = 1.0f / g_Z[i];
}

// ---------------------------------------------------------------------------
// ctx[b,i,h*64+hd] = (sum_j E[bh][i][j]*V[bh][j][hd]) / Z.  128x64 tile.
// ---------------------------------------------------------------------------
__global__ __launch_bounds__(256)
void av_kernel()
{
    __shared__ __align__(16) float As[16][132];
    __shared__ __align__(16) float Vs[16][68];
    __shared__ float zin[128];

    const int tid = threadIdx.x;
    const int tx = tid & 15, ty = tid >> 4;
    const int bh = blockIdx.y;
    const int b = bh >> 4, h = bh & 15;
    const int bi0 = blockIdx.x * 128;

    const int lr = tid >> 1, lk = (tid & 1) * 8;
    const float* Eg = g_E + ((size_t)bh*NT + bi0 + lr)*NT + lk;
    const float* Vg = g_V + (size_t)bh*NT*HD;
    const int vk = tid >> 4, vc = (tid & 15) * 4;

    if (tid < 128) zin[tid] = g_Zi[(size_t)bh*NT + bi0 + tid];

    u64 acc[4][4];
    #pragma unroll
    for (int i = 0; i < 4; i++)
        #pragma unroll
        for (int j = 0; j < 4; j++) acc[i][j] = 0ull;

    for (int k0 = 0; k0 < NT; k0 += 16) {
        float4 a0 = *(const float4*)(Eg + k0);
        float4 a1 = *(const float4*)(Eg + k0 + 4);
        float4 v0 = *(const float4*)(Vg + (size_t)(k0 + vk)*HD + vc);
        __syncthreads();
        As[lk+0][lr]=a0.x; As[lk+1][lr]=a0.y; As[lk+2][lr]=a0.z; As[lk+3][lr]=a0.w;
        As[lk+4][lr]=a1.x; As[lk+5][lr]=a1.y; As[lk+6][lr]=a1.z; As[lk+7][lr]=a1.w;
        *(float4*)&Vs[vk][vc] = v0;
        __syncthreads();
        #pragma unroll
        for (int k = 0; k < 16; k++) {
            ulonglong2 m0 = *(const ulonglong2*)&As[k][ty*4];
            ulonglong2 m1 = *(const ulonglong2*)&As[k][64+ty*4];
            float4 b0 = *(const float4*)&Vs[k][tx*4];
            u64 ap[4] = {m0.x, m0.y, m1.x, m1.y};
            u64 bs4[4] = {splat2(b0.x),splat2(b0.y),splat2(b0.z),splat2(b0.w)};
            #pragma unroll
            for (int i = 0; i < 4; i++)
                #pragma unroll
                for (int j = 0; j < 4; j++)
                    fma2(acc[i][j], ap[i], bs4[j]);
        }
    }

    #pragma unroll
    for (int i = 0; i < 4; i++) {
        int r = (i < 2) ? ty*4 + 2*i : 64 + ty*4 + 2*(i-2);
        float zi0 = zin[r], zi1 = zin[r+1];
        float2 t[4];
        #pragma unroll
        for (int j = 0; j < 4; j++) t[j] = unpk(acc[i][j]);
        size_t base = ((size_t)b*NT + bi0 + r)*DM + h*HD + tx*4;
        *(float4*)(g_ctx + base)      = make_float4(t[0].x*zi0, t[1].x*zi0, t[2].x*zi0, t[3].x*zi0);
        *(float4*)(g_ctx + base + DM) = make_float4(t[0].y*zi1, t[1].y*zi1, t[2].y*zi1, t[3].y*zi1);
    }
}

// P = (mean_h p + EPS)^10, p = e * (1/Z)
__global__ __launch_bounds__(256)
void build_P_kernel()
{
    size_t idx = (size_t)blockIdx.x * 256 + threadIdx.x;
    size_t b = idx / ((size_t)NT*NT);
    size_t rem = idx - b * (size_t)NT*NT;
    int i = (int)(rem >> 11);
    float s = 0.f;
    #pragma unroll
    for (int h = 0; h < H; h++)
        s += g_E[(size_t)(b*H + h)*NT*NT + rem] * g_Zi[(size_t)(b*H + h)*NT + i];
    float avg = s * (1.0f / 16.0f);
    g_P[idx] = expf(logf(avg + EPSF) * 10.0f);
}

__global__ __launch_bounds__(256)
void rownorm_kernel()
{
    const size_t rowi = blockIdx.x;
    float* rp = g_P + rowi * NT;
    const int tid = threadIdx.x;
    __shared__ float red[256];
    float v[8]; float s = 0.f;
    #pragma unroll
    for (int k = 0; k < 8; k++) { v[k] = rp[tid + k*256]; s += v[k]; }
    red[tid] = s; __syncthreads();
    for (int o = 128; o > 0; o >>= 1) { if (tid < o) red[tid] += red[tid+o]; __syncthreads(); }
    float inv = 1.0f / (red[0] + EPSF);
    #pragma unroll
    for (int k = 0; k < 8; k++) rp[tid + k*256] = v[k] * inv;
}

__global__ __launch_bounds__(256)
void colsum_kernel()
{
    const int j = blockIdx.x * 256 + threadIdx.x;
    const int b = blockIdx.y;
    const float* p = g_P + (size_t)b*NT*NT + j;
    float s = 0.f;
    for (int i = 0; i < NT; i++) s += p[(size_t)i*NT];
    g_colsum[b*NT + j] = s;
}

// fused: divide by colsum, then row-normalize (bit-identical to separate passes)
__global__ __launch_bounds__(256)
void coldiv_rownorm_kernel()
{
    const size_t rowi = blockIdx.x;
    const int b = (int)(rowi >> 11);
    float* rp = g_P + rowi * NT;
    const int tid = threadIdx.x;
    __shared__ float red[256];
    float v[8]; float s = 0.f;
    #pragma unroll
    for (int k = 0; k < 8; k++) {
        int j = tid + k*256;
        v[k] = rp[j] / (g_colsum[b*NT + j] + EPSF);
        s += v[k];
    }
    red[tid] = s; __syncthreads();
    for (int o = 128; o > 0; o >>= 1) { if (tid < o) red[tid] += red[tid+o]; __syncthreads(); }
    float inv = 1.0f / (red[0] + EPSF);
    #pragma unroll
    for (int k = 0; k < 8; k++) rp[tid + k*256] = v[k] * inv;
}

__global__ __launch_bounds__(256)
void cert_kernel(const float* __restrict__ cert, const float* __restrict__ ctemp,
                 float* __restrict__ out)
{
    const int idx = blockIdx.x * 256 + threadIdx.x;
    const int b = idx >> 11, i = idx & 2047;
    float s = 0.f;
    #pragma unroll
    for (int h = 0; h < H; h++) {
        size_t o = (size_t)(b*H + h)*NT + i;
        float Z = g_Z[o];
        s += logf(Z) - g_T[o] / Z;
    }
    float ent = s * (1.0f / 16.0f);
    float z = ctemp[0] * (logf(2048.0f) - ent);
    out[idx] = fmaxf(cert[idx], 1.0f / (1.0f + expf(-z)));
}

// final coldiv fused into argmax (division result bit-identical to stored pass)
__global__ __launch_bounds__(256)
void argmax_gather_kernel(const int* __restrict__ perm, float* __restrict__ out)
{
    const int rowi = blockIdx.x;
    const int b = rowi >> 11;
    const float* rp = g_P + (size_t)rowi * NT;
    const int tid = threadIdx.x;
    __shared__ float bv[256];
    __shared__ int   bi[256];

    float best = -INFINITY; int bj = NT;
    #pragma unroll
    for (int s = 0; s < 8; s++) {
        int j = tid + s*256;
        float v = rp[j] / (g_colsum[b*NT + j] + EPSF);
        if (v > best) { best = v; bj = j; }
    }
    bv[tid] = best; bi[tid] = bj; __syncthreads();
    for (int o = 128; o > 0; o >>= 1) {
        if (tid < o) {
            if (bv[tid+o] > bv[tid] || (bv[tid+o] == bv[tid] && bi[tid+o] < bi[tid])) {
                bv[tid] = bv[tid+o]; bi[tid] = bi[tid+o];
            }
        }
        __syncthreads();
    }
    if (tid == 0) out[rowi] = (float)perm[(size_t)b*NT + bi[0]];
}

extern "C" void kernel_launch(void* const* d_in, const int* in_sizes, int n_in,
                              void* d_out, int out_size)
{
    const float* x     = (const float*)d_in[0];
    const float* cert  = (const float*)d_in[1];
    const int*   perm  = (const int*)  d_in[2];
    const float* Wq    = (const float*)d_in[3];
    const float* bq    = (const float*)d_in[4];
    const float* Wk    = (const float*)d_in[5];
    const float* bk    = (const float*)d_in[6];
    const float* Wv    = (const float*)d_in[7];
    const float* bvv   = (const float*)d_in[8];
    const float* Wo    = (const float*)d_in[9];
    const float* bo    = (const float*)d_in[10];
    const float* pbs   = (const float*)d_in[11];
    const float* ctemp = (const float*)d_in[12];
    float* out = (float*)d_out;

    float *pQ, *pK, *pV, *pCtx;
    cudaGetSymbolAddress((void**)&pQ,   g_Q);
    cudaGetSymbolAddress((void**)&pK,   g_K);
    cudaGetSymbolAddress((void**)&pV,   g_V);
    cudaGetSymbolAddress((void**)&pCtx, g_ctx);

    const int M = B * NT;                  // 4096

    dim3 gProj(DM/128, M/128);             // (8, 32)
    gemm_nt2<<<gProj, 256>>>(x, Wq, bq, pQ, DM, DM, 1);
    gemm_nt2<<<gProj, 256>>>(x, Wk, bk, pK, DM, DM, 1);
    gemm_nt2<<<gProj, 256>>>(x, Wv, bvv, pV, DM, DM, 1);

    dim3 gS(NT/128, B*H);                  // (16, 32)
    scores_exp_kernel<<<gS, 256>>>(pbs, perm);
    zinv_kernel<<<(B*H*NT)/256, 256>>>();

    av_kernel<<<gS, 256>>>();

    gemm_nt2<<<gProj, 256>>>(pCtx, Wo, bo, out, DM, DM, 0);

    cert_kernel<<<(B*NT)/256, 256>>>(cert, ctemp, out + (size_t)M*DM);

    build_P_kernel<<<32768, 256>>>();
    rownorm_kernel<<<B*NT, 256>>>();
    for (int it = 0; it < 10; it++) {
        colsum_kernel<<<dim3(NT/256, B), 256>>>();
        if (it < 9) coldiv_rownorm_kernel<<<B*NT, 256>>>();
    }
    argmax_gather_kernel<<<B*NT, 256>>>(perm, out + (size_t)M*DM + B*NT);
}

// round 4
// speedup vs baseline: 1.9747x; 1.4623x over previous
#include <cuda_runtime.h>
#include <math.h>

#define B   2
#define NT  2048
#define DM  1024
#define H   16
#define HD  64
#define EPSF 1e-10f

__device__ float g_Q[(size_t)B*H*NT*HD];
__device__ float g_K[(size_t)B*H*NT*HD];
__device__ float g_V[(size_t)B*H*NT*HD];
__device__ float g_E[(size_t)B*H*NT*NT];     // exp(scores), unnormalized
__device__ float g_P[(size_t)B*NT*NT];
__device__ float g_ctx[(size_t)B*NT*DM];
__device__ float g_Z[(size_t)B*H*NT];
__device__ float g_T[(size_t)B*H*NT];
__device__ float g_Zi[(size_t)B*H*NT];
__device__ float g_colsum[B*NT];

__device__ __forceinline__ unsigned cvt_tf32(float x){
    unsigned r; asm("cvt.rna.tf32.f32 %0, %1;" : "=r"(r) : "f"(x)); return r;
}
__device__ __forceinline__ void mma_tf32(float4 &c,
    unsigned a0, unsigned a1, unsigned a2, unsigned a3,
    unsigned b0, unsigned b1)
{
    asm("mma.sync.aligned.m16n8k8.row.col.f32.tf32.tf32.f32 "
        "{%0,%1,%2,%3},{%4,%5,%6,%7},{%8,%9},{%0,%1,%2,%3};"
        : "+f"(c.x), "+f"(c.y), "+f"(c.z), "+f"(c.w)
        : "r"(a0), "r"(a1), "r"(a2), "r"(a3), "r"(b0), "r"(b1));
}

// ---------------------------------------------------------------------------
// C[m][e] = sum_k A[m][k]*W[e][k] + bias[e].  128x128 tile, BK=16, tf32 mma.
// 8 warps: 2 in M x 4 in N; warp tile 64x32 = 4x4 m16n8 tiles.
// ---------------------------------------------------------------------------
__global__ __launch_bounds__(256)
void gemm_nt_mma(const float* __restrict__ A, const float* __restrict__ W,
                 const float* __restrict__ bias, float* __restrict__ C,
                 int N, int K, int head_layout)
{
    __shared__ unsigned As[16][136];
    __shared__ unsigned Bs[16][136];
    const int tid = threadIdx.x, lane = tid & 31, warp = tid >> 5;
    const int gid = lane >> 2, tig = lane & 3;
    const int wm = warp & 1, wn = warp >> 1;
    const int bm0 = blockIdx.y * 128, bn0 = blockIdx.x * 128;
    const int lr = tid >> 1, lk = (tid & 1) * 8;
    const float* Ag = A + (size_t)(bm0 + lr) * K + lk;
    const float* Wg = W + (size_t)(bn0 + lr) * K + lk;

    float4 acc[4][4];
    #pragma unroll
    for (int i = 0; i < 4; i++)
        #pragma unroll
        for (int j = 0; j < 4; j++) acc[i][j] = make_float4(0.f,0.f,0.f,0.f);

    for (int k0 = 0; k0 < K; k0 += 16) {
        float4 a0 = *(const float4*)(Ag + k0);
        float4 a1 = *(const float4*)(Ag + k0 + 4);
        float4 w0 = *(const float4*)(Wg + k0);
        float4 w1 = *(const float4*)(Wg + k0 + 4);
        __syncthreads();
        As[lk+0][lr]=cvt_tf32(a0.x); As[lk+1][lr]=cvt_tf32(a0.y);
        As[lk+2][lr]=cvt_tf32(a0.z); As[lk+3][lr]=cvt_tf32(a0.w);
        As[lk+4][lr]=cvt_tf32(a1.x); As[lk+5][lr]=cvt_tf32(a1.y);
        As[lk+6][lr]=cvt_tf32(a1.z); As[lk+7][lr]=cvt_tf32(a1.w);
        Bs[lk+0][lr]=cvt_tf32(w0.x); Bs[lk+1][lr]=cvt_tf32(w0.y);
        Bs[lk+2][lr]=cvt_tf32(w0.z); Bs[lk+3][lr]=cvt_tf32(w0.w);
        Bs[lk+4][lr]=cvt_tf32(w1.x); Bs[lk+5][lr]=cvt_tf32(w1.y);
        Bs[lk+6][lr]=cvt_tf32(w1.z); Bs[lk+7][lr]=cvt_tf32(w1.w);
        __syncthreads();
        #pragma unroll
        for (int ks = 0; ks < 2; ks++) {
            const int kb = ks * 8;
            unsigned af[4][4];
            #pragma unroll
            for (int mt = 0; mt < 4; mt++) {
                int m = wm*64 + mt*16 + gid;
                af[mt][0] = As[kb+tig][m];     af[mt][1] = As[kb+tig][m+8];
                af[mt][2] = As[kb+tig+4][m];   af[mt][3] = As[kb+tig+4][m+8];
            }
            #pragma unroll
            for (int nt = 0; nt < 4; nt++) {
                int n = wn*32 + nt*8 + gid;
                unsigned b0 = Bs[kb+tig][n], b1 = Bs[kb+tig+4][n];
                #pragma unroll
                for (int mt = 0; mt < 4; mt++)
                    mma_tf32(acc[mt][nt], af[mt][0],af[mt][1],af[mt][2],af[mt][3], b0, b1);
            }
        }
    }

    #pragma unroll
    for (int mt = 0; mt < 4; mt++) {
        int r0 = bm0 + wm*64 + mt*16 + gid;
        #pragma unroll
        for (int nt = 0; nt < 4; nt++) {
            int c0 = bn0 + wn*32 + nt*8 + tig*2;
            float bx = bias[c0], by = bias[c0+1];
            float2 lo = make_float2(acc[mt][nt].x + bx, acc[mt][nt].y + by);
            float2 hi = make_float2(acc[mt][nt].z + bx, acc[mt][nt].w + by);
            if (head_layout) {
                int bb = r0 >> 11, tok = r0 & 2047, hh = c0 >> 6, hd = c0 & 63;
                float* p = C + (((size_t)(bb*H + hh)*NT + tok)*HD) + hd;
                *(float2*)p = lo;
                *(float2*)(p + 8*HD) = hi;
            } else {
                float* p = C + (size_t)r0*N + c0;
                *(float2*)p = lo;
                *(float2*)(p + 8*(size_t)N) = hi;
            }
        }
    }
}

// ---------------------------------------------------------------------------
// Fused scores + exp + row Z/T with tf32 mma.  Block = 128 rows of one (b,h).
// ---------------------------------------------------------------------------
__global__ __launch_bounds__(256)
void scores_exp_mma(const float* __restrict__ pbs, const int* __restrict__ perm)
{
    __shared__ unsigned Qs[64][136];
    __shared__ unsigned Ks[16][136];
    __shared__ float pfi[128], pfj[128];

    const int tid = threadIdx.x, lane = tid & 31, warp = tid >> 5;
    const int gid = lane >> 2, tig = lane & 3;
    const int wm = warp & 1, wn = warp >> 1;
    const int bh = blockIdx.y, b = bh >> 4, h = bh & 15;
    const int bi0 = blockIdx.x * 128;
    const float pb = fabsf(pbs[h]);

    const float* Qg = g_Q + ((size_t)bh*NT + bi0)*HD;
    const int lr = tid >> 1, lk = (tid & 1) * 8;
    #pragma unroll
    for (int c = 0; c < 4; c++) {
        int kk = lk + c*16;
        float4 q0 = *(const float4*)(Qg + (size_t)lr*HD + kk);
        float4 q1 = *(const float4*)(Qg + (size_t)lr*HD + kk + 4);
        Qs[kk+0][lr]=cvt_tf32(q0.x); Qs[kk+1][lr]=cvt_tf32(q0.y);
        Qs[kk+2][lr]=cvt_tf32(q0.z); Qs[kk+3][lr]=cvt_tf32(q0.w);
        Qs[kk+4][lr]=cvt_tf32(q1.x); Qs[kk+5][lr]=cvt_tf32(q1.y);
        Qs[kk+6][lr]=cvt_tf32(q1.z); Qs[kk+7][lr]=cvt_tf32(q1.w);
    }
    if (tid < 128) pfi[tid] = (float)perm[b*NT + bi0 + tid];

    float Zr[8] = {0,0,0,0,0,0,0,0};
    float Tr[8] = {0,0,0,0,0,0,0,0};

    for (int j0 = 0; j0 < NT; j0 += 128) {
        __syncthreads();
        if (tid < 128) pfj[tid] = (float)perm[b*NT + j0 + tid];

        float4 acc[4][4];
        #pragma unroll
        for (int i = 0; i < 4; i++)
            #pragma unroll
            for (int j = 0; j < 4; j++) acc[i][j] = make_float4(0.f,0.f,0.f,0.f);

        const float* Kg = g_K + ((size_t)bh*NT + j0)*HD;
        #pragma unroll
        for (int kc = 0; kc < 64; kc += 16) {
            float4 k0v = *(const float4*)(Kg + (size_t)lr*HD + kc + lk);
            float4 k1v = *(const float4*)(Kg + (size_t)lr*HD + kc + lk + 4);
            __syncthreads();
            Ks[lk+0][lr]=cvt_tf32(k0v.x); Ks[lk+1][lr]=cvt_tf32(k0v.y);
            Ks[lk+2][lr]=cvt_tf32(k0v.z); Ks[lk+3][lr]=cvt_tf32(k0v.w);
            Ks[lk+4][lr]=cvt_tf32(k1v.x); Ks[lk+5][lr]=cvt_tf32(k1v.y);
            Ks[lk+6][lr]=cvt_tf32(k1v.z); Ks[lk+7][lr]=cvt_tf32(k1v.w);
            __syncthreads();
            #pragma unroll
            for (int ks = 0; ks < 2; ks++) {
                const int kb = ks * 8;
                unsigned af[4][4];
                #pragma unroll
                for (int mt = 0; mt < 4; mt++) {
                    int m = wm*64 + mt*16 + gid;
                    af[mt][0] = Qs[kc+kb+tig][m];     af[mt][1] = Qs[kc+kb+tig][m+8];
                    af[mt][2] = Qs[kc+kb+tig+4][m];   af[mt][3] = Qs[kc+kb+tig+4][m+8];
                }
                #pragma unroll
                for (int nt = 0; nt < 4; nt++) {
                    int n = wn*32 + nt*8 + gid;
                    unsigned b0 = Ks[kb+tig][n], b1 = Ks[kb+tig+4][n];
                    #pragma unroll
                    for (int mt = 0; mt < 4; mt++)
                        mma_tf32(acc[mt][nt], af[mt][0],af[mt][1],af[mt][2],af[mt][3], b0, b1);
                }
            }
        }

        #pragma unroll
        for (int mt = 0; mt < 4; mt++) {
            int rl = wm*64 + mt*16 + gid;
            float pa = pfi[rl], pc = pfi[rl+8];
            #pragma unroll
            for (int nt = 0; nt < 4; nt++) {
                int cl = wn*32 + nt*8 + tig*2;
                float d0 = pfj[cl], d1 = pfj[cl+1];
                float4 a = acc[mt][nt];
                float s00 = a.x*0.125f - fabsf(pa - d0)*pb;
                float s01 = a.y*0.125f - fabsf(pa - d1)*pb;
                float s10 = a.z*0.125f - fabsf(pc - d0)*pb;
                float s11 = a.w*0.125f - fabsf(pc - d1)*pb;
                float e00 = __expf(s00), e01 = __expf(s01);
                float e10 = __expf(s10), e11 = __expf(s11);
                Zr[mt*2]   += e00 + e01;  Tr[mt*2]   += s00*e00 + s01*e01;
                Zr[mt*2+1] += e10 + e11;  Tr[mt*2+1] += s10*e10 + s11*e11;
                size_t base = ((size_t)bh*NT + bi0 + rl)*NT + j0 + cl;
                *(float2*)(g_E + base)        = make_float2(e00, e01);
                *(float2*)(g_E + base + 8*NT) = make_float2(e10, e11);
            }
        }
    }

    // block reduction of Z/T: 16 partials per row (wn x tig)
    float* red = (float*)&Qs[0][0];
    const int pcol = wn*4 + tig;
    __syncthreads();
    #pragma unroll
    for (int mt = 0; mt < 4; mt++) {
        int r0 = wm*64 + mt*16 + gid;
        red[pcol*128 + r0]     = Zr[mt*2];
        red[pcol*128 + r0 + 8] = Zr[mt*2+1];
    }
    __syncthreads();
    if (tid < 128) {
        float s = 0.f;
        #pragma unroll
        for (int t = 0; t < 16; t++) s += red[t*128 + tid];
        g_Z[(size_t)bh*NT + bi0 + tid] = s;
    }
    __syncthreads();
    #pragma unroll
    for (int mt = 0; mt < 4; mt++) {
        int r0 = wm*64 + mt*16 + gid;
        red[pcol*128 + r0]     = Tr[mt*2];
        red[pcol*128 + r0 + 8] = Tr[mt*2+1];
    }
    __syncthreads();
    if (tid < 128) {
        float s = 0.f;
        #pragma unroll
        for (int t = 0; t < 16; t++) s += red[t*128 + tid];
        g_T[(size_t)bh*NT + bi0 + tid] = s;
    }
}

__global__ __launch_bounds__(256)
void zinv_kernel()
{
    int i = blockIdx.x * 256 + threadIdx.x;
    g_Zi[i] = 1.0f / g_Z[i];
}

// ---------------------------------------------------------------------------
// ctx = (E @ V) / Z with tf32 mma.  Block 128x64; 8 warps = 4M x 2N (32x32).
// ---------------------------------------------------------------------------
__global__ __launch_bounds__(256)
void av_mma()
{
    __shared__ unsigned As[16][136];
    __shared__ unsigned Vs[16][72];
    __shared__ float zin[128];

    const int tid = threadIdx.x, lane = tid & 31, warp = tid >> 5;
    const int gid = lane >> 2, tig = lane & 3;
    const int wm = warp >> 1, wn = warp & 1;
    const int bh = blockIdx.y, b = bh >> 4, h = bh & 15;
    const int bi0 = blockIdx.x * 128;

    const int lr = tid >> 1, lk = (tid & 1) * 8;
    const float* Eg = g_E + ((size_t)bh*NT + bi0 + lr)*NT + lk;
    const float* Vg = g_V + (size_t)bh*NT*HD;
    const int vk = tid >> 4, vc = (tid & 15) * 4;

    if (tid < 128) zin[tid] = g_Zi[(size_t)bh*NT + bi0 + tid];

    float4 acc[2][4];
    #pragma unroll
    for (int i = 0; i < 2; i++)
        #pragma unroll
        for (int j = 0; j < 4; j++) acc[i][j] = make_float4(0.f,0.f,0.f,0.f);

    for (int k0 = 0; k0 < NT; k0 += 16) {
        float4 a0 = *(const float4*)(Eg + k0);
        float4 a1 = *(const float4*)(Eg + k0 + 4);
        float4 vv = *(const float4*)(Vg + (size_t)(k0 + vk)*HD + vc);
        __syncthreads();
        As[lk+0][lr]=cvt_tf32(a0.x); As[lk+1][lr]=cvt_tf32(a0.y);
        As[lk+2][lr]=cvt_tf32(a0.z); As[lk+3][lr]=cvt_tf32(a0.w);
        As[lk+4][lr]=cvt_tf32(a1.x); As[lk+5][lr]=cvt_tf32(a1.y);
        As[lk+6][lr]=cvt_tf32(a1.z); As[lk+7][lr]=cvt_tf32(a1.w);
        Vs[vk][vc+0]=cvt_tf32(vv.x); Vs[vk][vc+1]=cvt_tf32(vv.y);
        Vs[vk][vc+2]=cvt_tf32(vv.z); Vs[vk][vc+3]=cvt_tf32(vv.w);
        __syncthreads();
        #pragma unroll
        for (int ks = 0; ks < 2; ks++) {
            const int kb = ks * 8;
            unsigned af[2][4];
            #pragma unroll
            for (int mt = 0; mt < 2; mt++) {
                int m = wm*32 + mt*16 + gid;
                af[mt][0] = As[kb+tig][m];     af[mt][1] = As[kb+tig][m+8];
                af[mt][2] = As[kb+tig+4][m];   af[mt][3] = As[kb+tig+4][m+8];
            }
            #pragma unroll
            for (int nt = 0; nt < 4; nt++) {
                int n = wn*32 + nt*8 + gid;
                unsigned b0 = Vs[kb+tig][n], b1 = Vs[kb+tig+4][n];
                #pragma unroll
                for (int mt = 0; mt < 2; mt++)
                    mma_tf32(acc[mt][nt], af[mt][0],af[mt][1],af[mt][2],af[mt][3], b0, b1);
            }
        }
    }

    #pragma unroll
    for (int mt = 0; mt < 2; mt++) {
        int rl = wm*32 + mt*16 + gid;
        float z0 = zin[rl], z1 = zin[rl+8];
        #pragma unroll
        for (int nt = 0; nt < 4; nt++) {
            int cl = wn*32 + nt*8 + tig*2;
            float4 a = acc[mt][nt];
            size_t base = ((size_t)b*NT + bi0 + rl)*DM + h*HD + cl;
            *(float2*)(g_ctx + base)        = make_float2(a.x*z0, a.y*z0);
            *(float2*)(g_ctx + base + 8*DM) = make_float2(a.z*z1, a.w*z1);
        }
    }
}

// P = (mean_h p + EPS)^10, p = e * (1/Z)
__global__ __launch_bounds__(256)
void build_P_kernel()
{
    size_t idx = (size_t)blockIdx.x * 256 + threadIdx.x;
    size_t b = idx / ((size_t)NT*NT);
    size_t rem = idx - b * (size_t)NT*NT;
    int i = (int)(rem >> 11);
    float s = 0.f;
    #pragma unroll
    for (int h = 0; h < H; h++)
        s += g_E[(size_t)(b*H + h)*NT*NT + rem] * g_Zi[(size_t)(b*H + h)*NT + i];
    float avg = s * (1.0f / 16.0f);
    g_P[idx] = expf(logf(avg + EPSF) * 10.0f);
}

__global__ __launch_bounds__(256)
void rownorm_kernel()
{
    const size_t rowi = blockIdx.x;
    float* rp = g_P + rowi * NT;
    const int tid = threadIdx.x;
    __shared__ float red[256];
    float v[8]; float s = 0.f;
    #pragma unroll
    for (int k = 0; k < 8; k++) { v[k] = rp[tid + k*256]; s += v[k]; }
    red[tid] = s; __syncthreads();
    for (int o = 128; o > 0; o >>= 1) { if (tid < o) red[tid] += red[tid+o]; __syncthreads(); }
    float inv = 1.0f / (red[0] + EPSF);
    #pragma unroll
    for (int k = 0; k < 8; k++) rp[tid + k*256] = v[k] * inv;
}

__global__ __launch_bounds__(256)
void colsum_kernel()
{
    const int j = blockIdx.x * 256 + threadIdx.x;
    const int b = blockIdx.y;
    const float* p = g_P + (size_t)b*NT*NT + j;
    float s = 0.f;
    for (int i = 0; i < NT; i++) s += p[(size_t)i*NT];
    g_colsum[b*NT + j] = s;
}

__global__ __launch_bounds__(256)
void coldiv_rownorm_kernel()
{
    const size_t rowi = blockIdx.x;
    const int b = (int)(rowi >> 11);
    float* rp = g_P + rowi * NT;
    const int tid = threadIdx.x;
    __shared__ float red[256];
    float v[8]; float s = 0.f;
    #pragma unroll
    for (int k = 0; k < 8; k++) {
        int j = tid + k*256;
        v[k] = rp[j] / (g_colsum[b*NT + j] + EPSF);
        s += v[k];
    }
    red[tid] = s; __syncthreads();
    for (int o = 128; o > 0; o >>= 1) { if (tid < o) red[tid] += red[tid+o]; __syncthreads(); }
    float inv = 1.0f / (red[0] + EPSF);
    #pragma unroll
    for (int k = 0; k < 8; k++) rp[tid + k*256] = v[k] * inv;
}

__global__ __launch_bounds__(256)
void cert_kernel(const float* __restrict__ cert, const float* __restrict__ ctemp,
                 float* __restrict__ out)
{
    const int idx = blockIdx.x * 256 + threadIdx.x;
    const int b = idx >> 11, i = idx & 2047;
    float s = 0.f;
    #pragma unroll
    for (int h = 0; h < H; h++) {
        size_t o = (size_t)(b*H + h)*NT + i;
        float Z = g_Z[o];
        s += logf(Z) - g_T[o] / Z;
    }
    float ent = s * (1.0f / 16.0f);
    float z = ctemp[0] * (logf(2048.0f) - ent);
    out[idx] = fmaxf(cert[idx], 1.0f / (1.0f + expf(-z)));
}

__global__ __launch_bounds__(256)
void argmax_gather_kernel(const int* __restrict__ perm, float* __restrict__ out)
{
    const int rowi = blockIdx.x;
    const int b = rowi >> 11;
    const float* rp = g_P + (size_t)rowi * NT;
    const int tid = threadIdx.x;
    __shared__ float bv[256];
    __shared__ int   bi[256];

    float best = -INFINITY; int bj = NT;
    #pragma unroll
    for (int s = 0; s < 8; s++) {
        int j = tid + s*256;
        float v = rp[j] / (g_colsum[b*NT + j] + EPSF);
        if (v > best) { best = v; bj = j; }
    }
    bv[tid] = best; bi[tid] = bj; __syncthreads();
    for (int o = 128; o > 0; o >>= 1) {
        if (tid < o) {
            if (bv[tid+o] > bv[tid] || (bv[tid+o] == bv[tid] && bi[tid+o] < bi[tid])) {
                bv[tid] = bv[tid+o]; bi[tid] = bi[tid+o];
            }
        }
        __syncthreads();
    }
    if (tid == 0) out[rowi] = (float)perm[(size_t)b*NT + bi[0]];
}

extern "C" void kernel_launch(void* const* d_in, const int* in_sizes, int n_in,
                              void* d_out, int out_size)
{
    const float* x     = (const float*)d_in[0];
    const float* cert  = (const float*)d_in[1];
    const int*   perm  = (const int*)  d_in[2];
    const float* Wq    = (const float*)d_in[3];
    const float* bq    = (const float*)d_in[4];
    const float* Wk    = (const float*)d_in[5];
    const float* bk    = (const float*)d_in[6];
    const float* Wv    = (const float*)d_in[7];
    const float* bvv   = (const float*)d_in[8];
    const float* Wo    = (const float*)d_in[9];
    const float* bo    = (const float*)d_in[10];
    const float* pbs   = (const float*)d_in[11];
    const float* ctemp = (const float*)d_in[12];
    float* out = (float*)d_out;

    float *pQ, *pK, *pV, *pCtx;
    cudaGetSymbolAddress((void**)&pQ,   g_Q);
    cudaGetSymbolAddress((void**)&pK,   g_K);
    cudaGetSymbolAddress((void**)&pV,   g_V);
    cudaGetSymbolAddress((void**)&pCtx, g_ctx);

    const int M = B * NT;                  // 4096

    dim3 gProj(DM/128, M/128);             // (8, 32)
    gemm_nt_mma<<<gProj, 256>>>(x, Wq, bq, pQ, DM, DM, 1);
    gemm_nt_mma<<<gProj, 256>>>(x, Wk, bk, pK, DM, DM, 1);
    gemm_nt_mma<<<gProj, 256>>>(x, Wv, bvv, pV, DM, DM, 1);

    dim3 gS(NT/128, B*H);                  // (16, 32)
    scores_exp_mma<<<gS, 256>>>(pbs, perm);
    zinv_kernel<<<(B*H*NT)/256, 256>>>();

    av_mma<<<gS, 256>>>();

    gemm_nt_mma<<<gProj, 256>>>(pCtx, Wo, bo, out, DM, DM, 0);

    cert_kernel<<<(B*NT)/256, 256>>>(cert, ctemp, out + (size_t)M*DM);

    build_P_kernel<<<32768, 256>>>();
    rownorm_kernel<<<B*NT, 256>>>();
    for (int it = 0; it < 10; it++) {
        colsum_kernel<<<dim3(NT/256, B), 256>>>();
        if (it < 9) coldiv_rownorm_kernel<<<B*NT, 256>>>();
    }
    argmax_gather_kernel<<<B*NT, 256>>>(perm, out + (size_t)M*DM + B*NT);
}

// round 5
// speedup vs baseline: 2.4958x; 1.2639x over previous
#include <cuda_runtime.h>
#include <math.h>

#define B   2
#define NT  2048
#define DM  1024
#define H   16
#define HD  64
#define EPSF 1e-10f

__device__ float g_Q[(size_t)B*H*NT*HD];
__device__ float g_K[(size_t)B*H*NT*HD];
__device__ float g_V[(size_t)B*H*NT*HD];
__device__ float g_E[(size_t)B*H*NT*NT];     // exp(scores), unnormalized
__device__ float g_P[(size_t)B*NT*NT];
__device__ float g_ctx[(size_t)B*NT*DM];
__device__ float g_Z[(size_t)B*H*NT];
__device__ float g_T[(size_t)B*H*NT];
__device__ float g_Zi[(size_t)B*H*NT];
__device__ float g_colsum[B*NT];
__device__ float g_colpart[16*B*NT];

__device__ __forceinline__ unsigned cvt_tf32(float x){
    unsigned r; asm("cvt.rna.tf32.f32 %0, %1;" : "=r"(r) : "f"(x)); return r;
}
__device__ __forceinline__ void mma_tf32(float4 &c,
    unsigned a0, unsigned a1, unsigned a2, unsigned a3,
    unsigned b0, unsigned b1)
{
    asm("mma.sync.aligned.m16n8k8.row.col.f32.tf32.tf32.f32 "
        "{%0,%1,%2,%3},{%4,%5,%6,%7},{%8,%9},{%0,%1,%2,%3};"
        : "+f"(c.x), "+f"(c.y), "+f"(c.z), "+f"(c.w)
        : "r"(a0), "r"(a1), "r"(a2), "r"(a3), "r"(b0), "r"(b1));
}

// ---------------------------------------------------------------------------
// C[m][e] = sum_k A[m][k]*W[e][k] + bias[e].  128x128 tile, BK=16, tf32 mma.
// ---------------------------------------------------------------------------
__global__ __launch_bounds__(256, 2)
void gemm_nt_mma(const float* __restrict__ A, const float* __restrict__ W,
                 const float* __restrict__ bias, float* __restrict__ C,
                 int N, int K, int head_layout)
{
    __shared__ unsigned As[16][136];
    __shared__ unsigned Bs[16][136];
    const int tid = threadIdx.x, lane = tid & 31, warp = tid >> 5;
    const int gid = lane >> 2, tig = lane & 3;
    const int wm = warp & 1, wn = warp >> 1;
    const int bm0 = blockIdx.y * 128, bn0 = blockIdx.x * 128;
    const int lr = tid >> 1, lk = (tid & 1) * 8;
    const float* Ag = A + (size_t)(bm0 + lr) * K + lk;
    const float* Wg = W + (size_t)(bn0 + lr) * K + lk;

    float4 acc[4][4];
    #pragma unroll
    for (int i = 0; i < 4; i++)
        #pragma unroll
        for (int j = 0; j < 4; j++) acc[i][j] = make_float4(0.f,0.f,0.f,0.f);

    for (int k0 = 0; k0 < K; k0 += 16) {
        float4 a0 = *(const float4*)(Ag + k0);
        float4 a1 = *(const float4*)(Ag + k0 + 4);
        float4 w0 = *(const float4*)(Wg + k0);
        float4 w1 = *(const float4*)(Wg + k0 + 4);
        __syncthreads();
        As[lk+0][lr]=cvt_tf32(a0.x); As[lk+1][lr]=cvt_tf32(a0.y);
        As[lk+2][lr]=cvt_tf32(a0.z); As[lk+3][lr]=cvt_tf32(a0.w);
        As[lk+4][lr]=cvt_tf32(a1.x); As[lk+5][lr]=cvt_tf32(a1.y);
        As[lk+6][lr]=cvt_tf32(a1.z); As[lk+7][lr]=cvt_tf32(a1.w);
        Bs[lk+0][lr]=cvt_tf32(w0.x); Bs[lk+1][lr]=cvt_tf32(w0.y);
        Bs[lk+2][lr]=cvt_tf32(w0.z); Bs[lk+3][lr]=cvt_tf32(w0.w);
        Bs[lk+4][lr]=cvt_tf32(w1.x); Bs[lk+5][lr]=cvt_tf32(w1.y);
        Bs[lk+6][lr]=cvt_tf32(w1.z); Bs[lk+7][lr]=cvt_tf32(w1.w);
        __syncthreads();
        #pragma unroll
        for (int ks = 0; ks < 2; ks++) {
            const int kb = ks * 8;
            unsigned af[4][4];
            #pragma unroll
            for (int mt = 0; mt < 4; mt++) {
                int m = wm*64 + mt*16 + gid;
                af[mt][0] = As[kb+tig][m];     af[mt][1] = As[kb+tig][m+8];
                af[mt][2] = As[kb+tig+4][m];   af[mt][3] = As[kb+tig+4][m+8];
            }
            #pragma unroll
            for (int nt = 0; nt < 4; nt++) {
                int n = wn*32 + nt*8 + gid;
                unsigned b0 = Bs[kb+tig][n], b1 = Bs[kb+tig+4][n];
                #pragma unroll
                for (int mt = 0; mt < 4; mt++)
                    mma_tf32(acc[mt][nt], af[mt][0],af[mt][1],af[mt][2],af[mt][3], b0, b1);
            }
        }
    }

    #pragma unroll
    for (int mt = 0; mt < 4; mt++) {
        int r0 = bm0 + wm*64 + mt*16 + gid;
        #pragma unroll
        for (int nt = 0; nt < 4; nt++) {
            int c0 = bn0 + wn*32 + nt*8 + tig*2;
            float bx = bias[c0], by = bias[c0+1];
            float2 lo = make_float2(acc[mt][nt].x + bx, acc[mt][nt].y + by);
            float2 hi = make_float2(acc[mt][nt].z + bx, acc[mt][nt].w + by);
            if (head_layout) {
                int bb = r0 >> 11, tok = r0 & 2047, hh = c0 >> 6, hd = c0 & 63;
                float* p = C + (((size_t)(bb*H + hh)*NT + tok)*HD) + hd;
                *(float2*)p = lo;
                *(float2*)(p + 8*HD) = hi;
            } else {
                float* p = C + (size_t)r0*N + c0;
                *(float2*)p = lo;
                *(float2*)(p + 8*(size_t)N) = hi;
            }
        }
    }
}

// ---------------------------------------------------------------------------
// Fused scores + exp + row Z/T/Zi with tf32 mma.
// ---------------------------------------------------------------------------
__global__ __launch_bounds__(256, 2)
void scores_exp_mma(const float* __restrict__ pbs, const int* __restrict__ perm)
{
    __shared__ unsigned Qs[64][136];
    __shared__ unsigned Ks[16][136];
    __shared__ float pfi[128], pfj[128];

    const int tid = threadIdx.x, lane = tid & 31, warp = tid >> 5;
    const int gid = lane >> 2, tig = lane & 3;
    const int wm = warp & 1, wn = warp >> 1;
    const int bh = blockIdx.y, b = bh >> 4, h = bh & 15;
    const int bi0 = blockIdx.x * 128;
    const float pb = fabsf(pbs[h]);

    const float* Qg = g_Q + ((size_t)bh*NT + bi0)*HD;
    const int lr = tid >> 1, lk = (tid & 1) * 8;
    #pragma unroll
    for (int c = 0; c < 4; c++) {
        int kk = lk + c*16;
        float4 q0 = *(const float4*)(Qg + (size_t)lr*HD + kk);
        float4 q1 = *(const float4*)(Qg + (size_t)lr*HD + kk + 4);
        Qs[kk+0][lr]=cvt_tf32(q0.x); Qs[kk+1][lr]=cvt_tf32(q0.y);
        Qs[kk+2][lr]=cvt_tf32(q0.z); Qs[kk+3][lr]=cvt_tf32(q0.w);
        Qs[kk+4][lr]=cvt_tf32(q1.x); Qs[kk+5][lr]=cvt_tf32(q1.y);
        Qs[kk+6][lr]=cvt_tf32(q1.z); Qs[kk+7][lr]=cvt_tf32(q1.w);
    }
    if (tid < 128) pfi[tid] = (float)perm[b*NT + bi0 + tid];

    float Zr[8] = {0,0,0,0,0,0,0,0};
    float Tr[8] = {0,0,0,0,0,0,0,0};

    for (int j0 = 0; j0 < NT; j0 += 128) {
        __syncthreads();
        if (tid < 128) pfj[tid] = (float)perm[b*NT + j0 + tid];

        float4 acc[4][4];
        #pragma unroll
        for (int i = 0; i < 4; i++)
            #pragma unroll
            for (int j = 0; j < 4; j++) acc[i][j] = make_float4(0.f,0.f,0.f,0.f);

        const float* Kg = g_K + ((size_t)bh*NT + j0)*HD;
        #pragma unroll
        for (int kc = 0; kc < 64; kc += 16) {
            float4 k0v = *(const float4*)(Kg + (size_t)lr*HD + kc + lk);
            float4 k1v = *(const float4*)(Kg + (size_t)lr*HD + kc + lk + 4);
            __syncthreads();
            Ks[lk+0][lr]=cvt_tf32(k0v.x); Ks[lk+1][lr]=cvt_tf32(k0v.y);
            Ks[lk+2][lr]=cvt_tf32(k0v.z); Ks[lk+3][lr]=cvt_tf32(k0v.w);
            Ks[lk+4][lr]=cvt_tf32(k1v.x); Ks[lk+5][lr]=cvt_tf32(k1v.y);
            Ks[lk+6][lr]=cvt_tf32(k1v.z); Ks[lk+7][lr]=cvt_tf32(k1v.w);
            __syncthreads();
            #pragma unroll
            for (int ks = 0; ks < 2; ks++) {
                const int kb = ks * 8;
                unsigned af[4][4];
                #pragma unroll
                for (int mt = 0; mt < 4; mt++) {
                    int m = wm*64 + mt*16 + gid;
                    af[mt][0] = Qs[kc+kb+tig][m];     af[mt][1] = Qs[kc+kb+tig][m+8];
                    af[mt][2] = Qs[kc+kb+tig+4][m];   af[mt][3] = Qs[kc+kb+tig+4][m+8];
                }
                #pragma unroll
                for (int nt = 0; nt < 4; nt++) {
                    int n = wn*32 + nt*8 + gid;
                    unsigned b0 = Ks[kb+tig][n], b1 = Ks[kb+tig+4][n];
                    #pragma unroll
                    for (int mt = 0; mt < 4; mt++)
                        mma_tf32(acc[mt][nt], af[mt][0],af[mt][1],af[mt][2],af[mt][3], b0, b1);
                }
            }
        }

        #pragma unroll
        for (int mt = 0; mt < 4; mt++) {
            int rl = wm*64 + mt*16 + gid;
            float pa = pfi[rl], pc = pfi[rl+8];
            #pragma unroll
            for (int nt = 0; nt < 4; nt++) {
                int cl = wn*32 + nt*8 + tig*2;
                float d0 = pfj[cl], d1 = pfj[cl+1];
                float4 a = acc[mt][nt];
                float s00 = a.x*0.125f - fabsf(pa - d0)*pb;
                float s01 = a.y*0.125f - fabsf(pa - d1)*pb;
                float s10 = a.z*0.125f - fabsf(pc - d0)*pb;
                float s11 = a.w*0.125f - fabsf(pc - d1)*pb;
                float e00 = __expf(s00), e01 = __expf(s01);
                float e10 = __expf(s10), e11 = __expf(s11);
                Zr[mt*2]   += e00 + e01;  Tr[mt*2]   += s00*e00 + s01*e01;
                Zr[mt*2+1] += e10 + e11;  Tr[mt*2+1] += s10*e10 + s11*e11;
                size_t base = ((size_t)bh*NT + bi0 + rl)*NT + j0 + cl;
                *(float2*)(g_E + base)        = make_float2(e00, e01);
                *(float2*)(g_E + base + 8*NT) = make_float2(e10, e11);
            }
        }
    }

    float* red = (float*)&Qs[0][0];
    const int pcol = wn*4 + tig;
    __syncthreads();
    #pragma unroll
    for (int mt = 0; mt < 4; mt++) {
        int r0 = wm*64 + mt*16 + gid;
        red[pcol*128 + r0]     = Zr[mt*2];
        red[pcol*128 + r0 + 8] = Zr[mt*2+1];
    }
    __syncthreads();
    if (tid < 128) {
        float s = 0.f;
        #pragma unroll
        for (int t = 0; t < 16; t++) s += red[t*128 + tid];
        g_Z[(size_t)bh*NT + bi0 + tid]  = s;
        g_Zi[(size_t)bh*NT + bi0 + tid] = 1.0f / s;
    }
    __syncthreads();
    #pragma unroll
    for (int mt = 0; mt < 4; mt++) {
        int r0 = wm*64 + mt*16 + gid;
        red[pcol*128 + r0]     = Tr[mt*2];
        red[pcol*128 + r0 + 8] = Tr[mt*2+1];
    }
    __syncthreads();
    if (tid < 128) {
        float s = 0.f;
        #pragma unroll
        for (int t = 0; t < 16; t++) s += red[t*128 + tid];
        g_T[(size_t)bh*NT + bi0 + tid] = s;
    }
}

// ---------------------------------------------------------------------------
// ctx = (E @ V) / Z with tf32 mma.  Block 128x64.
// ---------------------------------------------------------------------------
__global__ __launch_bounds__(256, 2)
void av_mma()
{
    __shared__ unsigned As[16][136];
    __shared__ unsigned Vs[16][72];
    __shared__ float zin[128];

    const int tid = threadIdx.x, lane = tid & 31, warp = tid >> 5;
    const int gid = lane >> 2, tig = lane & 3;
    const int wm = warp >> 1, wn = warp & 1;
    const int bh = blockIdx.y, b = bh >> 4, h = bh & 15;
    const int bi0 = blockIdx.x * 128;

    const int lr = tid >> 1, lk = (tid & 1) * 8;
    const float* Eg = g_E + ((size_t)bh*NT + bi0 + lr)*NT + lk;
    const float* Vg = g_V + (size_t)bh*NT*HD;
    const int vk = tid >> 4, vc = (tid & 15) * 4;

    if (tid < 128) zin[tid] = g_Zi[(size_t)bh*NT + bi0 + tid];

    float4 acc[2][4];
    #pragma unroll
    for (int i = 0; i < 2; i++)
        #pragma unroll
        for (int j = 0; j < 4; j++) acc[i][j] = make_float4(0.f,0.f,0.f,0.f);

    for (int k0 = 0; k0 < NT; k0 += 16) {
        float4 a0 = *(const float4*)(Eg + k0);
        float4 a1 = *(const float4*)(Eg + k0 + 4);
        float4 vv = *(const float4*)(Vg + (size_t)(k0 + vk)*HD + vc);
        __syncthreads();
        As[lk+0][lr]=cvt_tf32(a0.x); As[lk+1][lr]=cvt_tf32(a0.y);
        As[lk+2][lr]=cvt_tf32(a0.z); As[lk+3][lr]=cvt_tf32(a0.w);
        As[lk+4][lr]=cvt_tf32(a1.x); As[lk+5][lr]=cvt_tf32(a1.y);
        As[lk+6][lr]=cvt_tf32(a1.z); As[lk+7][lr]=cvt_tf32(a1.w);
        Vs[vk][vc+0]=cvt_tf32(vv.x); Vs[vk][vc+1]=cvt_tf32(vv.y);
        Vs[vk][vc+2]=cvt_tf32(vv.z); Vs[vk][vc+3]=cvt_tf32(vv.w);
        __syncthreads();
        #pragma unroll
        for (int ks = 0; ks < 2; ks++) {
            const int kb = ks * 8;
            unsigned af[2][4];
            #pragma unroll
            for (int mt = 0; mt < 2; mt++) {
                int m = wm*32 + mt*16 + gid;
                af[mt][0] = As[kb+tig][m];     af[mt][1] = As[kb+tig][m+8];
                af[mt][2] = As[kb+tig+4][m];   af[mt][3] = As[kb+tig+4][m+8];
            }
            #pragma unroll
            for (int nt = 0; nt < 4; nt++) {
                int n = wn*32 + nt*8 + gid;
                unsigned b0 = Vs[kb+tig][n], b1 = Vs[kb+tig+4][n];
                #pragma unroll
                for (int mt = 0; mt < 2; mt++)
                    mma_tf32(acc[mt][nt], af[mt][0],af[mt][1],af[mt][2],af[mt][3], b0, b1);
            }
        }
    }

    #pragma unroll
    for (int mt = 0; mt < 2; mt++) {
        int rl = wm*32 + mt*16 + gid;
        float z0 = zin[rl], z1 = zin[rl+8];
        #pragma unroll
        for (int nt = 0; nt < 4; nt++) {
            int cl = wn*32 + nt*8 + tig*2;
            float4 a = acc[mt][nt];
            size_t base = ((size_t)b*NT + bi0 + rl)*DM + h*HD + cl;
            *(float2*)(g_ctx + base)        = make_float2(a.x*z0, a.y*z0);
            *(float2*)(g_ctx + base + 8*DM) = make_float2(a.z*z1, a.w*z1);
        }
    }
}

// ---------------------------------------------------------------------------
// build_P fused with first row-normalization.  Block per row (b,i).
// P_row = (mean_h E/Z + EPS)^10; then P_row /= (sum + EPS).
// ---------------------------------------------------------------------------
__global__ __launch_bounds__(256)
void build_P_rownorm()
{
    const int rowi = blockIdx.x;                  // 0..B*NT-1
    const int b = rowi >> 11, i = rowi & 2047;
    const int tid = threadIdx.x;
    __shared__ float red[256];

    float v[8] = {0,0,0,0,0,0,0,0};
    #pragma unroll
    for (int h = 0; h < H; h++) {
        const float* ep = g_E + ((size_t)(b*H + h)*NT + i)*NT;
        float zi = g_Zi[(size_t)(b*H + h)*NT + i];
        #pragma unroll
        for (int k = 0; k < 8; k++)
            v[k] += ep[tid + k*256] * zi;
    }
    float s = 0.f;
    #pragma unroll
    for (int k = 0; k < 8; k++) {
        v[k] = expf(logf(v[k] * (1.0f/16.0f) + EPSF) * 10.0f);
        s += v[k];
    }
    red[tid] = s; __syncthreads();
    for (int o = 128; o > 0; o >>= 1) { if (tid < o) red[tid] += red[tid+o]; __syncthreads(); }
    float inv = 1.0f / (red[0] + EPSF);
    float* rp = g_P + (size_t)rowi * NT;
    #pragma unroll
    for (int k = 0; k < 8; k++) rp[tid + k*256] = v[k] * inv;
}

// ---------------------------------------------------------------------------
// Parallel column sums: partial over 128-row slabs, then combine.
// ---------------------------------------------------------------------------
__global__ __launch_bounds__(256)
void colsum_part()
{
    const int j  = blockIdx.x * 256 + threadIdx.x;  // column
    const int ch = blockIdx.y;                       // row chunk 0..15
    const int b  = blockIdx.z;
    const float* p = g_P + (size_t)b*NT*NT + (size_t)ch*128*NT + j;
    float s = 0.f;
    #pragma unroll 8
    for (int i = 0; i < 128; i++) s += p[(size_t)i*NT];
    g_colpart[(ch*B + b)*NT + j] = s;
}

__global__ __launch_bounds__(256)
void colsum_combine()
{
    const int idx = blockIdx.x * 256 + threadIdx.x;  // 0..B*NT-1
    const int b = idx >> 11, j = idx & 2047;
    float s = 0.f;
    #pragma unroll
    for (int ch = 0; ch < 16; ch++) s += g_colpart[(ch*B + b)*NT + j];
    g_colsum[idx] = s;
}

__global__ __launch_bounds__(256)
void coldiv_rownorm_kernel()
{
    const size_t rowi = blockIdx.x;
    const int b = (int)(rowi >> 11);
    float* rp = g_P + rowi * NT;
    const int tid = threadIdx.x;
    __shared__ float red[256];
    float v[8]; float s = 0.f;
    #pragma unroll
    for (int k = 0; k < 8; k++) {
        int j = tid + k*256;
        v[k] = rp[j] / (g_colsum[b*NT + j] + EPSF);
        s += v[k];
    }
    red[tid] = s; __syncthreads();
    for (int o = 128; o > 0; o >>= 1) { if (tid < o) red[tid] += red[tid+o]; __syncthreads(); }
    float inv = 1.0f / (red[0] + EPSF);
    #pragma unroll
    for (int k = 0; k < 8; k++) rp[tid + k*256] = v[k] * inv;
}

__global__ __launch_bounds__(256)
void cert_kernel(const float* __restrict__ cert, const float* __restrict__ ctemp,
                 float* __restrict__ out)
{
    const int idx = blockIdx.x * 256 + threadIdx.x;
    const int b = idx >> 11, i = idx & 2047;
    float s = 0.f;
    #pragma unroll
    for (int h = 0; h < H; h++) {
        size_t o = (size_t)(b*H + h)*NT + i;
        float Z = g_Z[o];
        s += logf(Z) - g_T[o] / Z;
    }
    float ent = s * (1.0f / 16.0f);
    float z = ctemp[0] * (logf(2048.0f) - ent);
    out[idx] = fmaxf(cert[idx], 1.0f / (1.0f + expf(-z)));
}

__global__ __launch_bounds__(256)
void argmax_gather_kernel(const int* __restrict__ perm, float* __restrict__ out)
{
    const int rowi = blockIdx.x;
    const int b = rowi >> 11;
    const float* rp = g_P + (size_t)rowi * NT;
    const int tid = threadIdx.x;
    __shared__ float bv[256];
    __shared__ int   bi[256];

    float best = -INFINITY; int bj = NT;
    #pragma unroll
    for (int s = 0; s < 8; s++) {
        int j = tid + s*256;
        float v = rp[j] / (g_colsum[b*NT + j] + EPSF);
        if (v > best) { best = v; bj = j; }
    }
    bv[tid] = best; bi[tid] = bj; __syncthreads();
    for (int o = 128; o > 0; o >>= 1) {
        if (tid < o) {
            if (bv[tid+o] > bv[tid] || (bv[tid+o] == bv[tid] && bi[tid+o] < bi[tid])) {
                bv[tid] = bv[tid+o]; bi[tid] = bi[tid+o];
            }
        }
        __syncthreads();
    }
    if (tid == 0) out[rowi] = (float)perm[(size_t)b*NT + bi[0]];
}

extern "C" void kernel_launch(void* const* d_in, const int* in_sizes, int n_in,
                              void* d_out, int out_size)
{
    const float* x     = (const float*)d_in[0];
    const float* cert  = (const float*)d_in[1];
    const int*   perm  = (const int*)  d_in[2];
    const float* Wq    = (const float*)d_in[3];
    const float* bq    = (const float*)d_in[4];
    const float* Wk    = (const float*)d_in[5];
    const float* bk    = (const float*)d_in[6];
    const float* Wv    = (const float*)d_in[7];
    const float* bvv   = (const float*)d_in[8];
    const float* Wo    = (const float*)d_in[9];
    const float* bo    = (const float*)d_in[10];
    const float* pbs   = (const float*)d_in[11];
    const float* ctemp = (const float*)d_in[12];
    float* out = (float*)d_out;

    float *pQ, *pK, *pV, *pCtx;
    cudaGetSymbolAddress((void**)&pQ,   g_Q);
    cudaGetSymbolAddress((void**)&pK,   g_K);
    cudaGetSymbolAddress((void**)&pV,   g_V);
    cudaGetSymbolAddress((void**)&pCtx, g_ctx);

    const int M = B * NT;                  // 4096

    dim3 gProj(DM/128, M/128);             // (8, 32)
    gemm_nt_mma<<<gProj, 256>>>(x, Wq, bq, pQ, DM, DM, 1);
    gemm_nt_mma<<<gProj, 256>>>(x, Wk, bk, pK, DM, DM, 1);
    gemm_nt_mma<<<gProj, 256>>>(x, Wv, bvv, pV, DM, DM, 1);

    dim3 gS(NT/128, B*H);                  // (16, 32)
    scores_exp_mma<<<gS, 256>>>(pbs, perm);

    av_mma<<<gS, 256>>>();

    gemm_nt_mma<<<gProj, 256>>>(pCtx, Wo, bo, out, DM, DM, 0);

    cert_kernel<<<(B*NT)/256, 256>>>(cert, ctemp, out + (size_t)M*DM);

    build_P_rownorm<<<B*NT, 256>>>();
    for (int it = 0; it < 10; it++) {
        colsum_part<<<dim3(NT/256, 16, B), 256>>>();
        colsum_combine<<<(B*NT)/256, 256>>>();
        if (it < 9) coldiv_rownorm_kernel<<<B*NT, 256>>>();
    }
    argmax_gather_kernel<<<B*NT, 256>>>(perm, out + (size_t)M*DM + B*NT);
}